// round 7
// baseline (speedup 1.0000x reference)
#include <cuda_runtime.h>
#include <cuda_fp16.h>
#include <cstdint>

// Problem constants (fixed by the dataset)
#define NNODES 50000
#define FIN    128
#define HDIM   128
#define FOUTD  64
#define NEDGES 800000

// ---------------- scratch (device globals; no allocation allowed) -------------
__device__ __half g_h1 [NNODES * HDIM];    // x @ W1   (fp16 for gather traffic)
__device__ __half g_h2 [NNODES * FOUTD];   // fused(gather1,GEMM2) output (fp16)
__device__ float  g_dinv[NNODES];
__device__ int    g_deg [NNODES];
__device__ int    g_rowptr[NNODES];
__device__ int    g_cursor[NNODES];
__device__ int2   g_adj [NEDGES];
__device__ int    g_total;

// ---------------- packed f32x2 / async helpers --------------------------------
__device__ __forceinline__ void ffma2(unsigned long long& d, unsigned long long a,
                                      unsigned long long b) {
    asm("fma.rn.f32x2 %0, %1, %2, %0;" : "+l"(d) : "l"(a), "l"(b));
}
__device__ __forceinline__ unsigned long long pk(float x, float y) {
    unsigned long long r;
    asm("mov.b64 %0, {%1, %2};" : "=l"(r) : "f"(x), "f"(y));
    return r;
}
__device__ __forceinline__ float2 upk(unsigned long long v) {
    float2 r;
    asm("mov.b64 {%0, %1}, %2;" : "=f"(r.x), "=f"(r.y) : "l"(v));
    return r;
}
__device__ __forceinline__ uint32_t smem_u32(const void* p) {
    uint32_t a;
    asm("{ .reg .u64 t; cvta.to.shared.u64 t, %1; cvt.u32.u64 %0, t; }" : "=r"(a) : "l"(p));
    return a;
}
__device__ __forceinline__ void cpasync16(uint32_t dst, const void* src, int sz) {
    asm volatile("cp.async.cg.shared.global [%0], [%1], 16, %2;"
                 :: "r"(dst), "l"(src), "r"(sz) : "memory");
}
#define CP_COMMIT() asm volatile("cp.async.commit_group;" ::: "memory")
#define CP_WAIT1()  asm volatile("cp.async.wait_group 1;" ::: "memory")
#define CP_WAIT0()  asm volatile("cp.async.wait_group 0;" ::: "memory")

// ---------------- degree / CSR -------------------------------------------------
__global__ void k_zero_deg(int n) {
    int i = blockIdx.x * blockDim.x + threadIdx.x;
    if (i < n) g_deg[i] = 0;
    if (i == 0) g_total = 0;
}

__global__ void k_count(const int* __restrict__ ei, int e) {
    int i = blockIdx.x * blockDim.x + threadIdx.x;
    if (i < e) atomicAdd(&g_deg[ei[e + i]], 1);
}

// Single-pass scan: per-block exclusive scan + atomic base.
__global__ void k_scan_one(int n) {
    __shared__ int wsum[8];
    __shared__ int sbase;
    const int tid  = threadIdx.x;
    const int i    = blockIdx.x * 256 + tid;
    const int lane = tid & 31, wid = tid >> 5;

    int v = (i < n) ? g_deg[i] : 0;
    if (i < n) g_dinv[i] = rsqrtf((float)(v + 1));  // + self loop
    int x = v;
    #pragma unroll
    for (int off = 1; off < 32; off <<= 1) {
        int y = __shfl_up_sync(0xffffffffu, x, off);
        if (lane >= off) x += y;
    }
    if (lane == 31) wsum[wid] = x;
    __syncthreads();
    if (wid == 0) {
        int w = (lane < 8) ? wsum[lane] : 0;
        #pragma unroll
        for (int off = 1; off < 8; off <<= 1) {
            int y = __shfl_up_sync(0xffffffffu, w, off);
            if (lane >= off) w += y;
        }
        if (lane < 8) wsum[lane] = w;
    }
    __syncthreads();
    int base = (wid > 0) ? wsum[wid - 1] : 0;
    int excl = base + x - v;
    if (tid == 0) sbase = atomicAdd(&g_total, wsum[7]);
    __syncthreads();
    if (i < n) {
        int p = sbase + excl;
        g_rowptr[i] = p;
        g_cursor[i] = p;
    }
}

__global__ void k_fill(const int* __restrict__ ei, int e) {
    int i = blockIdx.x * blockDim.x + threadIdx.x;
    if (i >= e) return;
    int s = ei[i];
    int d = ei[e + i];
    float nrm = g_dinv[s] * g_dinv[d];
    int pos = atomicAdd(&g_cursor[d], 1);
    g_adj[pos] = make_int2(s, __float_as_int(nrm));
}

// ---------------- GEMM1: h1[n,128] = X[n,128] @ W1[128,128], cp.async DB ------
#define XKS 20   // Xs row stride: 16 k-floats + pad 4 (80B, 16B-aligned)

__device__ __forceinline__ void g1_load_chunk(
    int tid, int row0, int c, int buf,
    const float* __restrict__ X, const float* __restrict__ W,
    uint32_t xsb, uint32_t wsb, int n)
{
    #pragma unroll
    for (int q = 0; q < 2; q++) {
        int s = tid + q * 256;
        int r = s >> 2, kq = s & 3;
        int row = row0 + r;
        int rc = (row < n) ? row : 0;
        const float* src = X + (size_t)rc * 128 + c * 16 + kq * 4;
        int sz = (row < n) ? 16 : 0;
        uint32_t dst = xsb + (uint32_t)((buf * 128 + r) * XKS + kq * 4) * 4u;
        cpasync16(dst, src, sz);
    }
    #pragma unroll
    for (int q = 0; q < 2; q++) {
        int s = tid + q * 256;
        int k = s >> 5, cq = s & 31;
        const float* src = W + (size_t)(c * 16 + k) * 128 + cq * 4;
        uint32_t dst = wsb + (uint32_t)((buf * 16 + k) * 128 + cq * 4) * 4u;
        cpasync16(dst, src, 16);
    }
}

__global__ void __launch_bounds__(256, 3)
k_gemm1(const float* __restrict__ X, const float* __restrict__ W,
        __half* __restrict__ Y, int n)
{
    __shared__ float Xs[2][128][XKS];   // row-major chunk [m][k]
    __shared__ float Ws[2][16][128];    // [k][c]

    const int tid  = threadIdx.x;
    const int tx   = tid & 15;
    const int ty   = tid >> 4;
    const int row0 = blockIdx.x * 128;
    uint32_t xsb = smem_u32(&Xs[0][0][0]);
    uint32_t wsb = smem_u32(&Ws[0][0][0]);

    g1_load_chunk(tid, row0, 0, 0, X, W, xsb, wsb, n); CP_COMMIT();
    g1_load_chunk(tid, row0, 1, 1, X, W, xsb, wsb, n); CP_COMMIT();

    unsigned long long acc[8][4];
    #pragma unroll
    for (int i = 0; i < 8; i++)
        #pragma unroll
        for (int j = 0; j < 4; j++) acc[i][j] = 0ull;

    #pragma unroll
    for (int c = 0; c < 8; c++) {
        if (c < 7) { CP_WAIT1(); } else { CP_WAIT0(); }
        __syncthreads();
        const int buf = c & 1;

        #pragma unroll
        for (int k = 0; k < 16; k++) {
            float4 b0 = *(const float4*)&Ws[buf][k][tx * 4];
            float4 b1 = *(const float4*)&Ws[buf][k][64 + tx * 4];
            unsigned long long bp0 = pk(b0.x, b0.y);
            unsigned long long bp1 = pk(b0.z, b0.w);
            unsigned long long bp2 = pk(b1.x, b1.y);
            unsigned long long bp3 = pk(b1.z, b1.w);
            #pragma unroll
            for (int r = 0; r < 8; r++) {
                int rr = (r < 4) ? (ty * 4 + r) : (64 + ty * 4 + r - 4);
                float av = Xs[buf][rr][k];
                unsigned long long ap = pk(av, av);
                ffma2(acc[r][0], ap, bp0);
                ffma2(acc[r][1], ap, bp1);
                ffma2(acc[r][2], ap, bp2);
                ffma2(acc[r][3], ap, bp3);
            }
        }
        __syncthreads();
        if (c < 6) { g1_load_chunk(tid, row0, c + 2, buf, X, W, xsb, wsb, n); CP_COMMIT(); }
    }

    // ---- epilogue: fp32 -> fp16 ----
    #pragma unroll
    for (int r = 0; r < 8; r++) {
        int row = row0 + ((r < 4) ? (ty * 4 + r) : (64 + ty * 4 + r - 4));
        if (row < n) {
            float2 u0 = upk(acc[r][0]);
            float2 u1 = upk(acc[r][1]);
            float2 u2 = upk(acc[r][2]);
            float2 u3 = upk(acc[r][3]);
            __half2 p0 = __floats2half2_rn(u0.x, u0.y);
            __half2 p1 = __floats2half2_rn(u1.x, u1.y);
            __half2 p2 = __floats2half2_rn(u2.x, u2.y);
            __half2 p3 = __floats2half2_rn(u3.x, u3.y);
            uint2 s0 = make_uint2(*(uint32_t*)&p0, *(uint32_t*)&p1);
            uint2 s1 = make_uint2(*(uint32_t*)&p2, *(uint32_t*)&p3);
            *(uint2*)&Y[(size_t)row * 128 + tx * 4]      = s0;
            *(uint2*)&Y[(size_t)row * 128 + 64 + tx * 4] = s1;
        }
    }
}

// ---------------- fused: gather(conv1 agg)+b1+PReLU -> smem z -> @W2 -> h2 ----
// Block: 64 nodes, 512 threads (16 warps; warp gathers 4 nodes).
// zs [64][132] (m-major), W2s [128][68] (k-major). GEMM: tile 2m x 4c / thread.
__global__ void __launch_bounds__(512, 2)
k_gg(const __half* __restrict__ h1, const float* __restrict__ b1,
     const float* __restrict__ W2, const float* __restrict__ pa,
     __half* __restrict__ h2, int n)
{
    extern __shared__ float fsm[];
    float* zs  = fsm;              // [64][132]
    float* W2s = fsm + 64 * 132;   // [128][68]

    const int tid  = threadIdx.x;
    const int lane = tid & 31;
    const int w    = tid >> 5;
    const int nb0  = blockIdx.x * 64;

    // load W2 into smem: 2048 float4
    const float4* Wv = (const float4*)W2;
    #pragma unroll
    for (int q = 0; q < 4; q++) {
        int s = tid + q * 512;
        int k = s >> 4, cq = s & 15;
        *(float4*)&W2s[k * 68 + cq * 4] = Wv[s];
    }

    // ---- gather phase: warp w -> nodes nb0 + 4w .. 4w+3 ----
    const uint2* hv = (const uint2*)h1;
    float a  = *pa;
    float4 bb = ((const float4*)b1)[lane];

    #pragma unroll
    for (int i = 0; i < 4; i++) {
        int node = nb0 + w * 4 + i;
        if (node >= n) break;

        float di = g_dinv[node];
        float sw = di * di;
        uint2 raw = hv[(size_t)node * 32 + lane];
        float2 f0 = __half22float2(*(__half2*)&raw.x);
        float2 f1 = __half22float2(*(__half2*)&raw.y);
        float4 acc = make_float4(f0.x * sw, f0.y * sw, f1.x * sw, f1.y * sw);

        int e0 = g_rowptr[node];
        int e1 = e0 + g_deg[node];
        for (int e = e0; e < e1; e++) {
            int2 rec = __ldg(&g_adj[e]);
            float wt = __int_as_float(rec.y);
            uint2 rv = hv[(size_t)rec.x * 32 + lane];
            float2 v0 = __half22float2(*(__half2*)&rv.x);
            float2 v1 = __half22float2(*(__half2*)&rv.y);
            acc.x = fmaf(v0.x, wt, acc.x);
            acc.y = fmaf(v0.y, wt, acc.y);
            acc.z = fmaf(v1.x, wt, acc.z);
            acc.w = fmaf(v1.y, wt, acc.w);
        }

        acc.x += bb.x; acc.y += bb.y; acc.z += bb.z; acc.w += bb.w;
        acc.x = (acc.x >= 0.0f) ? acc.x : a * acc.x;
        acc.y = (acc.y >= 0.0f) ? acc.y : a * acc.y;
        acc.z = (acc.z >= 0.0f) ? acc.z : a * acc.z;
        acc.w = (acc.w >= 0.0f) ? acc.w : a * acc.w;

        int m = w * 4 + i;
        *(float4*)&zs[m * 132 + lane * 4] = acc;   // 528B rows: 16B-aligned
    }
    __syncthreads();

    // ---- mini-GEMM: out[m][c] = z[m][:] @ W2[:, c] ----
    const int tx = tid & 15;        // c = tx*4
    const int ty = tid >> 4;        // m pair = 2ty, 2ty+1

    unsigned long long acc2[2][2];
    acc2[0][0] = acc2[0][1] = acc2[1][0] = acc2[1][1] = 0ull;

    const float* za = zs + (ty * 2) * 132;
    const float* zb = za + 132;

    #pragma unroll 8
    for (int k = 0; k < 128; k++) {
        float4 b4 = *(const float4*)&W2s[k * 68 + tx * 4];
        unsigned long long bp0 = pk(b4.x, b4.y);
        unsigned long long bp1 = pk(b4.z, b4.w);
        float a0 = za[k], a1 = zb[k];
        unsigned long long ap0 = pk(a0, a0);
        unsigned long long ap1 = pk(a1, a1);
        ffma2(acc2[0][0], ap0, bp0);
        ffma2(acc2[0][1], ap0, bp1);
        ffma2(acc2[1][0], ap1, bp0);
        ffma2(acc2[1][1], ap1, bp1);
    }

    #pragma unroll
    for (int mi = 0; mi < 2; mi++) {
        int node = nb0 + ty * 2 + mi;
        if (node < n) {
            float2 u0 = upk(acc2[mi][0]);
            float2 u1 = upk(acc2[mi][1]);
            __half2 p0 = __floats2half2_rn(u0.x, u0.y);
            __half2 p1 = __floats2half2_rn(u1.x, u1.y);
            uint2 s0 = make_uint2(*(uint32_t*)&p0, *(uint32_t*)&p1);
            *(uint2*)&h2[(size_t)node * 64 + tx * 4] = s0;
        }
    }
}

// ---------------- gather64 (conv2 agg) + b2 + PReLU -> out --------------------
__global__ void k_gather64(const __half* __restrict__ h,
                           const float* __restrict__ b,
                           const float* __restrict__ pa,
                           float* __restrict__ out, int n)
{
    int g    = blockIdx.x * blockDim.x + threadIdx.x;
    int node = g >> 5;
    int lane = g & 31;
    if (node >= n) return;

    const __half2* hv = (const __half2*)h;

    float di = g_dinv[node];
    float sw = di * di;
    float2 f = __half22float2(hv[(size_t)node * 32 + lane]);
    float2 acc = make_float2(f.x * sw, f.y * sw);

    int e0 = g_rowptr[node];
    int e1 = e0 + g_deg[node];
    for (int e = e0; e < e1; e++) {
        int2 rec = __ldg(&g_adj[e]);
        float w  = __int_as_float(rec.y);
        float2 v = __half22float2(hv[(size_t)rec.x * 32 + lane]);
        acc.x = fmaf(v.x, w, acc.x);
        acc.y = fmaf(v.y, w, acc.y);
    }

    float a = *pa;
    float2 bb = ((const float2*)b)[lane];
    acc.x += bb.x; acc.y += bb.y;
    acc.x = (acc.x >= 0.0f) ? acc.x : a * acc.x;
    acc.y = (acc.y >= 0.0f) ? acc.y : a * acc.y;

    ((float2*)out)[(size_t)node * 32 + lane] = acc;
}

// ---------------- launch -------------------------------------------------------
extern "C" void kernel_launch(void* const* d_in, const int* in_sizes, int n_in,
                              void* d_out, int out_size)
{
    const float* x   = (const float*)d_in[0];
    const int*   ei  = (const int*)  d_in[1];
    const float* W1  = (const float*)d_in[2];
    const float* b1  = (const float*)d_in[3];
    const float* W2  = (const float*)d_in[4];
    const float* b2  = (const float*)d_in[5];
    const float* pa  = (const float*)d_in[6];
    float* out = (float*)d_out;

    const int n = in_sizes[0] / FIN;     // 50000
    const int e = in_sizes[1] / 2;       // 800000

    const int T = 256;
    __half* h1 = nullptr; cudaGetSymbolAddress((void**)&h1, g_h1);
    __half* h2 = nullptr; cudaGetSymbolAddress((void**)&h2, g_h2);

    const int nb   = (n + 255) / 256;
    const int gblk = (n + 127) / 128;
    const int fblk = (n + 63) / 64;

    const int smem_gg = (64 * 132 + 128 * 68) * sizeof(float);  // ~68.6 KB
    cudaFuncSetAttribute(k_gg, cudaFuncAttributeMaxDynamicSharedMemorySize, smem_gg);

    // Launch order: k_gemm1 is the 4th launch (observed ncu capture slot).
    k_zero_deg<<<(n + T - 1) / T, T>>>(n);                       // 1
    k_count   <<<(e + T - 1) / T, T>>>(ei, e);                   // 2
    k_scan_one<<<nb, 256>>>(n);                                  // 3 (+dinv)
    k_gemm1   <<<gblk, 256>>>(x, W1, h1, n);                     // 4 <- profiled
    k_fill    <<<(e + T - 1) / T, T>>>(ei, e);                   // 5
    k_gg      <<<fblk, 512, smem_gg>>>(h1, b1, W2, pa, h2, n);   // 6 (fused)
    {
        long long threads = (long long)n * 32;
        k_gather64<<<(int)((threads + T - 1) / T), T>>>(h2, b2, pa, out, n);  // 7
    }
}

// round 9
// speedup vs baseline: 2.3326x; 2.3326x over previous
#include <cuda_runtime.h>
#include <cuda_fp16.h>
#include <cstdint>

// Problem constants (fixed by the dataset)
#define NNODES 50000
#define FIN    128
#define HDIM   128
#define FOUTD  64
#define NEDGES 800000

// ---------------- scratch (device globals; no allocation allowed) -------------
__device__ __half g_h1 [NNODES * HDIM];    // x @ W1   (fp16 for gather traffic)
__device__ float  g_z1 [NNODES * HDIM];    // prelu(agg1 + b1)  (fp32 into GEMM2)
__device__ __half g_h2 [NNODES * FOUTD];   // z1 @ W2  (fp16)
__device__ float  g_dinv[NNODES];
__device__ int    g_deg [NNODES];
__device__ int    g_rowptr[NNODES];
__device__ int    g_cursor[NNODES];
__device__ int2   g_adj [NEDGES];
__device__ int    g_total;

// ---------------- packed f32x2 helpers ----------------------------------------
__device__ __forceinline__ void ffma2(unsigned long long& d, unsigned long long a,
                                      unsigned long long b) {
    asm("fma.rn.f32x2 %0, %1, %2, %0;" : "+l"(d) : "l"(a), "l"(b));
}
__device__ __forceinline__ unsigned long long pk(float x, float y) {
    unsigned long long r;
    asm("mov.b64 %0, {%1, %2};" : "=l"(r) : "f"(x), "f"(y));
    return r;
}
__device__ __forceinline__ float2 upk(unsigned long long v) {
    float2 r;
    asm("mov.b64 {%0, %1}, %2;" : "=f"(r.x), "=f"(r.y) : "l"(v));
    return r;
}

// ---------------- degree / CSR -------------------------------------------------
__global__ void k_zero_deg(int n) {
    int i = blockIdx.x * blockDim.x + threadIdx.x;
    if (i < n) g_deg[i] = 0;
    if (i == 0) g_total = 0;
}

__global__ void k_count(const int* __restrict__ ei, int e) {
    int i = blockIdx.x * blockDim.x + threadIdx.x;
    if (i < e) atomicAdd(&g_deg[ei[e + i]], 1);
}

// Single-pass scan: per-block exclusive scan + atomic base.
__global__ void k_scan_one(int n) {
    __shared__ int wsum[8];
    __shared__ int sbase;
    const int tid  = threadIdx.x;
    const int i    = blockIdx.x * 256 + tid;
    const int lane = tid & 31, wid = tid >> 5;

    int v = (i < n) ? g_deg[i] : 0;
    if (i < n) g_dinv[i] = rsqrtf((float)(v + 1));  // + self loop
    int x = v;
    #pragma unroll
    for (int off = 1; off < 32; off <<= 1) {
        int y = __shfl_up_sync(0xffffffffu, x, off);
        if (lane >= off) x += y;
    }
    if (lane == 31) wsum[wid] = x;
    __syncthreads();
    if (wid == 0) {
        int w = (lane < 8) ? wsum[lane] : 0;
        #pragma unroll
        for (int off = 1; off < 8; off <<= 1) {
            int y = __shfl_up_sync(0xffffffffu, w, off);
            if (lane >= off) w += y;
        }
        if (lane < 8) wsum[lane] = w;
    }
    __syncthreads();
    int base = (wid > 0) ? wsum[wid - 1] : 0;
    int excl = base + x - v;
    if (tid == 0) sbase = atomicAdd(&g_total, wsum[7]);
    __syncthreads();
    if (i < n) {
        int p = sbase + excl;
        g_rowptr[i] = p;
        g_cursor[i] = p;
    }
}

__global__ void k_fill(const int* __restrict__ ei, int e) {
    int i = blockIdx.x * blockDim.x + threadIdx.x;
    if (i >= e) return;
    int s = ei[i];
    int d = ei[e + i];
    float nrm = g_dinv[s] * g_dinv[d];
    int pos = atomicAdd(&g_cursor[d], 1);
    g_adj[pos] = make_int2(s, __float_as_int(nrm));
}

// ---------------- packed-fp32 GEMM: Y[n,BN] = X[n,128] @ W[128,BN], Y fp16 ----
// (round-6 kernel; register-prefetch double buffering, fma.rn.f32x2)
template<int BN>
__global__ void __launch_bounds__(2 * BN)
k_gemm_ff(const float* __restrict__ X, const float* __restrict__ W,
          __half* __restrict__ Y, int n)
{
    constexpr int NT  = 2 * BN;
    constexpr int TXN = BN / 8;
    constexpr int XSL = 512 / NT;
    constexpr int HB  = BN / 2;
    constexpr int BMP = 132;

    __shared__ float Xs[2][16][BMP];
    __shared__ float Ws[2][16][BN];

    const int tid  = threadIdx.x;
    const int tx   = tid & (TXN - 1);
    const int ty   = tid / TXN;
    const int row0 = blockIdx.x * 128;

    const float4* Xv = (const float4*)X;
    const float4* Wv = (const float4*)W;

    {
        #pragma unroll
        for (int q = 0; q < XSL; q++) {
            int s = tid + q * NT;
            int r = s >> 2, kq = s & 3;
            float4 v = make_float4(0.f, 0.f, 0.f, 0.f);
            if (row0 + r < n) v = Xv[(size_t)(row0 + r) * 32 + kq];
            Xs[0][kq * 4 + 0][r] = v.x;
            Xs[0][kq * 4 + 1][r] = v.y;
            Xs[0][kq * 4 + 2][r] = v.z;
            Xs[0][kq * 4 + 3][r] = v.w;
        }
        #pragma unroll
        for (int q = 0; q < 2; q++) {
            int s = tid + q * NT;
            int k = s / (BN / 4), cq = s % (BN / 4);
            *(float4*)&Ws[0][k][cq * 4] = Wv[k * (BN / 4) + cq];
        }
    }
    __syncthreads();

    unsigned long long acc[8][4];
    #pragma unroll
    for (int i = 0; i < 8; i++)
        #pragma unroll
        for (int j = 0; j < 4; j++) acc[i][j] = 0ull;

    #pragma unroll
    for (int c = 0; c < 8; c++) {
        const int buf = c & 1;

        float4 xr[XSL], wr[2];
        if (c < 7) {
            #pragma unroll
            for (int q = 0; q < XSL; q++) {
                int s = tid + q * NT;
                int r = s >> 2, kq = s & 3;
                xr[q] = make_float4(0.f, 0.f, 0.f, 0.f);
                if (row0 + r < n) xr[q] = Xv[(size_t)(row0 + r) * 32 + (c + 1) * 4 + kq];
            }
            #pragma unroll
            for (int q = 0; q < 2; q++) {
                int s = tid + q * NT;
                int k = s / (BN / 4), cq = s % (BN / 4);
                wr[q] = Wv[((c + 1) * 16 + k) * (BN / 4) + cq];
            }
        }

        #pragma unroll
        for (int k = 0; k < 16; k++) {
            float4 a0 = *(const float4*)&Xs[buf][k][ty * 4];
            float4 a1 = *(const float4*)&Xs[buf][k][64 + ty * 4];
            float4 b0 = *(const float4*)&Ws[buf][k][tx * 4];
            float4 b1 = *(const float4*)&Ws[buf][k][HB + tx * 4];

            unsigned long long bp0 = pk(b0.x, b0.y);
            unsigned long long bp1 = pk(b0.z, b0.w);
            unsigned long long bp2 = pk(b1.x, b1.y);
            unsigned long long bp3 = pk(b1.z, b1.w);

            float ar[8] = {a0.x, a0.y, a0.z, a0.w, a1.x, a1.y, a1.z, a1.w};
            #pragma unroll
            for (int r = 0; r < 8; r++) {
                unsigned long long ap = pk(ar[r], ar[r]);
                ffma2(acc[r][0], ap, bp0);
                ffma2(acc[r][1], ap, bp1);
                ffma2(acc[r][2], ap, bp2);
                ffma2(acc[r][3], ap, bp3);
            }
        }

        if (c < 7) {
            const int nb = buf ^ 1;
            #pragma unroll
            for (int q = 0; q < XSL; q++) {
                int s = tid + q * NT;
                int r = s >> 2, kq = s & 3;
                Xs[nb][kq * 4 + 0][r] = xr[q].x;
                Xs[nb][kq * 4 + 1][r] = xr[q].y;
                Xs[nb][kq * 4 + 2][r] = xr[q].z;
                Xs[nb][kq * 4 + 3][r] = xr[q].w;
            }
            #pragma unroll
            for (int q = 0; q < 2; q++) {
                int s = tid + q * NT;
                int k = s / (BN / 4), cq = s % (BN / 4);
                *(float4*)&Ws[nb][k][cq * 4] = wr[q];
            }
            __syncthreads();
        }
    }

    // ---- epilogue: fp32 -> fp16 ----
    #pragma unroll
    for (int r = 0; r < 8; r++) {
        int row = row0 + ((r < 4) ? (ty * 4 + r) : (64 + ty * 4 + r - 4));
        if (row < n) {
            float2 u0 = upk(acc[r][0]);
            float2 u1 = upk(acc[r][1]);
            float2 u2 = upk(acc[r][2]);
            float2 u3 = upk(acc[r][3]);
            __half2 p0 = __floats2half2_rn(u0.x, u0.y);
            __half2 p1 = __floats2half2_rn(u1.x, u1.y);
            __half2 p2 = __floats2half2_rn(u2.x, u2.y);
            __half2 p3 = __floats2half2_rn(u3.x, u3.y);
            uint2 s0 = make_uint2(*(uint32_t*)&p0, *(uint32_t*)&p1);
            uint2 s1 = make_uint2(*(uint32_t*)&p2, *(uint32_t*)&p3);
            *(uint2*)&Y[(size_t)row * BN + tx * 4]      = s0;
            *(uint2*)&Y[(size_t)row * BN + HB + tx * 4] = s1;
        }
    }
}

// ---------------- gather (warp per dst node), 4-edge unrolled ------------------
// Adjacency records loaded as int2 (8B-aligned always); 4 independent row loads
// in flight (MLP=4) before any FMA consumes them.
// conv1: h fp16 [N,128] (256B/row), out z1 fp32
__global__ void k_gather128(const __half* __restrict__ h,
                            const float* __restrict__ b,
                            const float* __restrict__ pa,
                            float* __restrict__ out, int n)
{
    int g    = blockIdx.x * blockDim.x + threadIdx.x;
    int node = g >> 5;
    int lane = g & 31;
    if (node >= n) return;

    const uint2* hv = (const uint2*)h;   // 8 B = 4 halves per lane

    float di = g_dinv[node];
    float sw = di * di;
    uint2 raw = hv[(size_t)node * 32 + lane];
    float2 f0 = __half22float2(*(__half2*)&raw.x);
    float2 f1 = __half22float2(*(__half2*)&raw.y);
    float4 acc = make_float4(f0.x * sw, f0.y * sw, f1.x * sw, f1.y * sw);

    const int e0 = g_rowptr[node];
    const int e1 = e0 + g_deg[node];
    int e = e0;

    for (; e + 4 <= e1; e += 4) {
        int2 r0 = __ldg(&g_adj[e]);
        int2 r1 = __ldg(&g_adj[e + 1]);
        int2 r2 = __ldg(&g_adj[e + 2]);
        int2 r3 = __ldg(&g_adj[e + 3]);
        uint2 v0 = hv[(size_t)r0.x * 32 + lane];
        uint2 v1 = hv[(size_t)r1.x * 32 + lane];
        uint2 v2 = hv[(size_t)r2.x * 32 + lane];
        uint2 v3 = hv[(size_t)r3.x * 32 + lane];
        float w0 = __int_as_float(r0.y);
        float w1 = __int_as_float(r1.y);
        float w2 = __int_as_float(r2.y);
        float w3 = __int_as_float(r3.y);

        float2 a0 = __half22float2(*(__half2*)&v0.x);
        float2 a1 = __half22float2(*(__half2*)&v0.y);
        acc.x = fmaf(a0.x, w0, acc.x); acc.y = fmaf(a0.y, w0, acc.y);
        acc.z = fmaf(a1.x, w0, acc.z); acc.w = fmaf(a1.y, w0, acc.w);
        a0 = __half22float2(*(__half2*)&v1.x);
        a1 = __half22float2(*(__half2*)&v1.y);
        acc.x = fmaf(a0.x, w1, acc.x); acc.y = fmaf(a0.y, w1, acc.y);
        acc.z = fmaf(a1.x, w1, acc.z); acc.w = fmaf(a1.y, w1, acc.w);
        a0 = __half22float2(*(__half2*)&v2.x);
        a1 = __half22float2(*(__half2*)&v2.y);
        acc.x = fmaf(a0.x, w2, acc.x); acc.y = fmaf(a0.y, w2, acc.y);
        acc.z = fmaf(a1.x, w2, acc.z); acc.w = fmaf(a1.y, w2, acc.w);
        a0 = __half22float2(*(__half2*)&v3.x);
        a1 = __half22float2(*(__half2*)&v3.y);
        acc.x = fmaf(a0.x, w3, acc.x); acc.y = fmaf(a0.y, w3, acc.y);
        acc.z = fmaf(a1.x, w3, acc.z); acc.w = fmaf(a1.y, w3, acc.w);
    }
    for (; e < e1; e++) {
        int2 rec = __ldg(&g_adj[e]);
        float w  = __int_as_float(rec.y);
        uint2 rv = hv[(size_t)rec.x * 32 + lane];
        float2 v0 = __half22float2(*(__half2*)&rv.x);
        float2 v1 = __half22float2(*(__half2*)&rv.y);
        acc.x = fmaf(v0.x, w, acc.x);
        acc.y = fmaf(v0.y, w, acc.y);
        acc.z = fmaf(v1.x, w, acc.z);
        acc.w = fmaf(v1.y, w, acc.w);
    }

    float a = *pa;
    float4 bb = ((const float4*)b)[lane];
    acc.x += bb.x; acc.y += bb.y; acc.z += bb.z; acc.w += bb.w;
    acc.x = (acc.x >= 0.0f) ? acc.x : a * acc.x;
    acc.y = (acc.y >= 0.0f) ? acc.y : a * acc.y;
    acc.z = (acc.z >= 0.0f) ? acc.z : a * acc.z;
    acc.w = (acc.w >= 0.0f) ? acc.w : a * acc.w;

    ((float4*)out)[(size_t)node * 32 + lane] = acc;
}

// conv2: h fp16 [N,64] (128B/row), out fp32 -> d_out
__global__ void k_gather64(const __half* __restrict__ h,
                           const float* __restrict__ b,
                           const float* __restrict__ pa,
                           float* __restrict__ out, int n)
{
    int g    = blockIdx.x * blockDim.x + threadIdx.x;
    int node = g >> 5;
    int lane = g & 31;
    if (node >= n) return;

    const __half2* hv = (const __half2*)h;   // 4 B = 2 halves per lane

    float di = g_dinv[node];
    float sw = di * di;
    float2 f = __half22float2(hv[(size_t)node * 32 + lane]);
    float2 acc = make_float2(f.x * sw, f.y * sw);

    const int e0 = g_rowptr[node];
    const int e1 = e0 + g_deg[node];
    int e = e0;

    for (; e + 4 <= e1; e += 4) {
        int2 r0 = __ldg(&g_adj[e]);
        int2 r1 = __ldg(&g_adj[e + 1]);
        int2 r2 = __ldg(&g_adj[e + 2]);
        int2 r3 = __ldg(&g_adj[e + 3]);
        __half2 h0 = hv[(size_t)r0.x * 32 + lane];
        __half2 h1 = hv[(size_t)r1.x * 32 + lane];
        __half2 h2 = hv[(size_t)r2.x * 32 + lane];
        __half2 h3 = hv[(size_t)r3.x * 32 + lane];
        float w0 = __int_as_float(r0.y);
        float w1 = __int_as_float(r1.y);
        float w2 = __int_as_float(r2.y);
        float w3 = __int_as_float(r3.y);

        float2 v;
        v = __half22float2(h0); acc.x = fmaf(v.x, w0, acc.x); acc.y = fmaf(v.y, w0, acc.y);
        v = __half22float2(h1); acc.x = fmaf(v.x, w1, acc.x); acc.y = fmaf(v.y, w1, acc.y);
        v = __half22float2(h2); acc.x = fmaf(v.x, w2, acc.x); acc.y = fmaf(v.y, w2, acc.y);
        v = __half22float2(h3); acc.x = fmaf(v.x, w3, acc.x); acc.y = fmaf(v.y, w3, acc.y);
    }
    for (; e < e1; e++) {
        int2 rec = __ldg(&g_adj[e]);
        float w  = __int_as_float(rec.y);
        float2 v = __half22float2(hv[(size_t)rec.x * 32 + lane]);
        acc.x = fmaf(v.x, w, acc.x);
        acc.y = fmaf(v.y, w, acc.y);
    }

    float a = *pa;
    float2 bb = ((const float2*)b)[lane];
    acc.x += bb.x; acc.y += bb.y;
    acc.x = (acc.x >= 0.0f) ? acc.x : a * acc.x;
    acc.y = (acc.y >= 0.0f) ? acc.y : a * acc.y;

    ((float2*)out)[(size_t)node * 32 + lane] = acc;
}

// ---------------- launch -------------------------------------------------------
extern "C" void kernel_launch(void* const* d_in, const int* in_sizes, int n_in,
                              void* d_out, int out_size)
{
    const float* x   = (const float*)d_in[0];
    const int*   ei  = (const int*)  d_in[1];
    const float* W1  = (const float*)d_in[2];
    const float* b1  = (const float*)d_in[3];
    const float* W2  = (const float*)d_in[4];
    const float* b2  = (const float*)d_in[5];
    const float* pa  = (const float*)d_in[6];
    float* out = (float*)d_out;

    const int n = in_sizes[0] / FIN;     // 50000
    const int e = in_sizes[1] / 2;       // 800000

    const int T = 256;
    __half* h1 = nullptr; cudaGetSymbolAddress((void**)&h1, g_h1);
    float*  z1 = nullptr; cudaGetSymbolAddress((void**)&z1, g_z1);
    __half* h2 = nullptr; cudaGetSymbolAddress((void**)&h2, g_h2);

    const int nb   = (n + 255) / 256;
    const int gblk = (n + 127) / 128;

    k_zero_deg<<<(n + T - 1) / T, T>>>(n);                             // 1
    k_count   <<<(e + T - 1) / T, T>>>(ei, e);                         // 2
    k_scan_one<<<nb, 256>>>(n);                                        // 3 (+dinv)
    k_fill    <<<(e + T - 1) / T, T>>>(ei, e);                         // 4
    k_gemm_ff<HDIM><<<gblk, 2 * HDIM>>>(x, W1, h1, n);                 // 5
    {
        long long threads = (long long)n * 32;
        k_gather128<<<(int)((threads + T - 1) / T), T>>>(h1, b1, pa, z1, n);  // 6
    }
    k_gemm_ff<FOUTD><<<gblk, 2 * FOUTD>>>(z1, W2, h2, n);              // 7
    {
        long long threads = (long long)n * 32;
        k_gather64<<<(int)((threads + T - 1) / T), T>>>(h2, b2, pa, out, n);  // 8
    }
}